// round 16
// baseline (speedup 1.0000x reference)
#include <cuda_runtime.h>
#include <cuda_bf16.h>
#include <float.h>

// ---------------------------------------------------------------------------
// HardBootstrappingLoss R15: R11/R14 persistent kernel with NT=256 and
// 6 CTAs/SM (grid 912). Same 48 warps/SM, but per-row serialized epilogue +
// load ramp now amortize over a 2x longer streaming window, and 6 independent
// rows per SM keep the load pipe busy through any one CTA's epilogue.
// ---------------------------------------------------------------------------

#define L2E 1.4426950408889634f
#define LN2 0.6931471805599453f
#define CAND_TH 3.0f       // N(0,1): E[#>TH per row] ~ 68; P(3rd-max < TH) ~ e^-68
#define CAP 1024
#define NT 256
#define NW (NT / 32)
#define GRID_P 912         // 6 CTAs/SM x 152 SMs (GB300)
#define FX_SCALE 67108864.0f   // 2^26 fixed-point for the loss sum

__device__ unsigned long long g_loss_fx = 0ULL;
__device__ int                g_cnt_tot = 0;
__device__ unsigned int       g_done    = 0;

__device__ __forceinline__ float ex2f(float x) {
    float y; asm("ex2.approx.f32 %0, %1;" : "=f"(y) : "f"(x)); return y;
}
__device__ __forceinline__ float lg2f(float x) {
    float y; asm("lg2.approx.f32 %0, %1;" : "=f"(y) : "f"(x)); return y;
}

struct Top3 { float v0, v1, v2; int i0, i1, i2; };

// tie-aware "greater": value desc, index asc (matches jax top_k/argmax)
__device__ __forceinline__ bool gtv(float v, int i, float u, int j) {
    return (v > u) || (v == u && i < j);
}
__device__ __forceinline__ void ins_tie(float x, int idx, Top3& t) {
    if (!gtv(x, idx, t.v2, t.i2)) return;
    if (gtv(x, idx, t.v1, t.i1)) {
        t.v2 = t.v1; t.i2 = t.i1;
        if (gtv(x, idx, t.v0, t.i0)) { t.v1 = t.v0; t.i1 = t.i0; t.v0 = x; t.i0 = idx; }
        else                          { t.v1 = x;   t.i1 = idx; }
    } else { t.v2 = x; t.i2 = idx; }
}
// fallback-only insert (per-thread ascending indices, caller checked x > v2)
__device__ __forceinline__ void ins(float x, int idx, Top3& t) {
    if (x > t.v1) {
        t.v2 = t.v1; t.i2 = t.i1;
        if (x > t.v0) { t.v1 = t.v0; t.i1 = t.i0; t.v0 = x; t.i0 = idx; }
        else          { t.v1 = x;    t.i1 = idx; }
    } else { t.v2 = x; t.i2 = idx; }
}

__device__ __forceinline__ void warp_top3(Top3& t) {
    const unsigned full = 0xFFFFFFFFu;
    #pragma unroll
    for (int off = 16; off > 0; off >>= 1) {
        float bv0 = __shfl_down_sync(full, t.v0, off);
        float bv1 = __shfl_down_sync(full, t.v1, off);
        float bv2 = __shfl_down_sync(full, t.v2, off);
        int   bi0 = __shfl_down_sync(full, t.i0, off);
        int   bi1 = __shfl_down_sync(full, t.i1, off);
        int   bi2 = __shfl_down_sync(full, t.i2, off);
        ins_tie(bv0, bi0, t);
        ins_tie(bv1, bi1, t);
        ins_tie(bv2, bi2, t);
    }
}

__global__ void __launch_bounds__(NT)
hb_main(const float* __restrict__ yp, const int* __restrict__ y,
        float* __restrict__ out, int B, int C) {
    const int tid = threadIdx.x;
    const int wid = tid >> 5, lid = tid & 31;

    __shared__ float s_val[CAP];
    __shared__ int   s_idx[CAP];
    __shared__ int   s_cnt;
    __shared__ float ssum[NW];
    __shared__ float fv0[NW], fv1[NW], fv2[NW];
    __shared__ int   fi0[NW], fi1[NW], fi2[NW];

    #define APPEND(x, idx)                                        \
        if ((x) > CAND_TH) {                                      \
            int _p = atomicAdd(&s_cnt, 1);                        \
            if (_p < CAP) { s_val[_p] = (x); s_idx[_p] = (idx); } \
        }

    #define SUM4(v)                                          \
        s0 += ex2f((v).x * L2E);                             \
        s1 += ex2f((v).y * L2E);                             \
        s2 += ex2f((v).z * L2E);                             \
        s3 += ex2f((v).w * L2E);

    #define M4(v) fmaxf(fmaxf((v).x, (v).y), fmaxf((v).z, (v).w))

    #define CAND4(v, idx)                    \
        if (M4(v) > CAND_TH) {               \
            APPEND((v).x, (idx))             \
            APPEND((v).y, (idx) + 1)         \
            APPEND((v).z, (idx) + 2)         \
            APPEND((v).w, (idx) + 3)         \
        }

    for (int row = blockIdx.x; row < B; row += gridDim.x) {
        const float* base = yp + (size_t)row * (size_t)C;

        if (tid == 0) s_cnt = 0;
        __syncthreads();

        float s0 = 0.0f, s1 = 0.0f, s2 = 0.0f, s3 = 0.0f;

        // alignment lead-in for 16B float4 loads (row offset C=50257 is odd)
        int pre = (int)((4u - (unsigned)(((size_t)row * (size_t)C) & 3u)) & 3u);
        if (pre > C) pre = C;
        const int n4   = (C - pre) >> 2;
        const int tail = C - pre - (n4 << 2);

        for (int k = tid; k < pre; k += NT) {
            float x = __ldg(base + k);
            s0 += ex2f(x * L2E);
            APPEND(x, k)
        }

        const float4* b4 = reinterpret_cast<const float4*>(base + pre);
        int j = tid;
        // 4 independent LDG.128 issued before any consumer (MLP_p1 = 4)
        for (; j + 3 * NT < n4; j += 4 * NT) {
            float4 a = __ldcs(b4 + j);
            float4 b = __ldcs(b4 + j + NT);
            float4 c = __ldcs(b4 + j + 2 * NT);
            float4 d = __ldcs(b4 + j + 3 * NT);
            SUM4(a) SUM4(b) SUM4(c) SUM4(d)
            int ia = pre + (j << 2);
            CAND4(a, ia)
            CAND4(b, ia + 1 * (NT << 2))
            CAND4(c, ia + 2 * (NT << 2))
            CAND4(d, ia + 3 * (NT << 2))
        }
        for (; j < n4; j += NT) {
            float4 a = __ldcs(b4 + j);
            int ia = pre + (j << 2);
            SUM4(a)
            CAND4(a, ia)
        }

        for (int k = tid; k < tail; k += NT) {
            int idx = C - tail + k;
            float x = __ldg(base + idx);
            s0 += ex2f(x * L2E);
            APPEND(x, idx)
        }

        // ---- block-reduce the exp sum (deterministic order) ----
        float sum = (s0 + s1) + (s2 + s3);
        const unsigned full = 0xFFFFFFFFu;
        #pragma unroll
        for (int off = 16; off > 0; off >>= 1)
            sum += __shfl_down_sync(full, sum, off);
        if (lid == 0) ssum[wid] = sum;
        __syncthreads();          // also makes s_cnt / candidates visible

        const int cnt = s_cnt;    // block-uniform
        Top3 t;
        t.v0 = t.v1 = t.v2 = -FLT_MAX;
        t.i0 = t.i1 = t.i2 = 0x7FFFFFFF;

        if (cnt >= 3 && cnt <= CAP) {
            // ---- fast path: top-3 from candidate buffer (warp 0 only) ----
            if (wid == 0) {
                for (int p = lid; p < cnt; p += 32) {
                    float x = s_val[p]; int ix = s_idx[p];
                    if (gtv(x, ix, t.v2, t.i2)) ins_tie(x, ix, t);
                }
                warp_top3(t);
            }
        } else {
            // ---- exact fallback (statistically never taken) ----
            for (int k = tid; k < C; k += NT) {
                float x = __ldg(base + k);
                if (x > t.v2) ins(x, k, t);
            }
            warp_top3(t);
            if (lid == 0) {
                fv0[wid] = t.v0; fv1[wid] = t.v1; fv2[wid] = t.v2;
                fi0[wid] = t.i0; fi1[wid] = t.i1; fi2[wid] = t.i2;
            }
            __syncthreads();
            if (wid == 0) {
                if (lid < NW) {
                    t.v0 = fv0[lid]; t.v1 = fv1[lid]; t.v2 = fv2[lid];
                    t.i0 = fi0[lid]; t.i1 = fi1[lid]; t.i2 = fi2[lid];
                } else {
                    t.v0 = t.v1 = t.v2 = -FLT_MAX;
                    t.i0 = t.i1 = t.i2 = 0x7FFFFFFF;
                }
                warp_top3(t);
            }
        }

        if (wid == 0) {
            float z = (lid < NW) ? ssum[lid] : 0.0f;
            #pragma unroll
            for (int off = 16; off > 0; off >>= 1)
                z += __shfl_down_sync(full, z, off);

            if (lid == 0) {
                const float Z    = z;
                const float logZ = lg2f(Z) * LN2;
                const float rz   = 1.0f / Z;

                const int   ycol  = __ldg(y + row);
                const float fyl   = __ldg(base + ycol);
                const float fy    = ex2f(fyl * L2E) * rz;
                const int   sflag = (fy < 0.02f) ? 1 : 0;

                const float e0 = ex2f(t.v0 * L2E);
                const float e1 = ex2f(t.v1 * L2E);
                const float e2 = ex2f(t.v2 * L2E);
                const float wa = (t.v0 * e0 + t.v1 * e1 + t.v2 * e2) / (e0 + e1 + e2);

                const float loss = sflag ? (logZ - wa) : (logZ - fyl);

                out[1 + row]             = (float)sflag;
                out[1 + B + row]         = sflag ? (float)t.i0 : -1.0f; // s*z_max
                out[1 + 2 * B + row]     = sflag ? (float)t.i1 : -1.0f; // s*max9_d
                out[1 + 3 * B + row]     = sflag ? (float)t.i2 : -1.0f; // s*max8_d
                out[1 + 4 * B + 1 + row] = sflag ? (e1 * rz) : 0.0f;    // s*max_9

                // deterministic fixed-point accumulation (integer = associative)
                long long fx = llrintf(loss * FX_SCALE);
                atomicAdd(&g_loss_fx, (unsigned long long)fx);
                atomicAdd(&g_cnt_tot, 1 - sflag);
            }
        }
        __syncthreads();   // smem (s_val/s_cnt/ssum) safe for next row
    }

    // ---- completion ticket: ONE thread per CTA, one fence per CTA ----
    if (tid == 0) {
        __threadfence();   // order this CTA's atomics/stores before the ticket
        unsigned v = atomicAdd(&g_done, 1u);
        if (v == gridDim.x - 1) {
            long long lv = (long long)atomicExch(&g_loss_fx, 0ULL); // read+reset
            int       cv = atomicExch(&g_cnt_tot, 0);
            out[0]         = (float)((double)lv / (double)FX_SCALE / (double)B);
            out[1 + 4 * B] = (float)cv;
            g_done = 0;    // reset for next graph replay (kernel-exit fences this)
        }
    }
}

extern "C" void kernel_launch(void* const* d_in, const int* in_sizes, int n_in,
                              void* d_out, int out_size) {
    const float* yp = (const float*)d_in[0];   // y_pred, fp32 [B, C]
    const int*   y  = (const int*)d_in[1];     // labels, int32 [B]
    const int B = in_sizes[1];
    const int C = in_sizes[0] / B;
    float* out = (float*)d_out;

    int grid = (B < GRID_P) ? B : GRID_P;
    hb_main<<<grid, NT>>>(yp, y, out, B, C);
}

// round 17
// speedup vs baseline: 1.0064x; 1.0064x over previous
#include <cuda_runtime.h>
#include <cuda_bf16.h>
#include <float.h>

// ---------------------------------------------------------------------------
// HardBootstrappingLoss R15: R11/R14 persistent kernel with NT=256 and
// 6 CTAs/SM (grid 912). Same 48 warps/SM, but per-row serialized epilogue +
// load ramp now amortize over a 2x longer streaming window, and 6 independent
// rows per SM keep the load pipe busy through any one CTA's epilogue.
// ---------------------------------------------------------------------------

#define L2E 1.4426950408889634f
#define LN2 0.6931471805599453f
#define CAND_TH 3.0f       // N(0,1): E[#>TH per row] ~ 68; P(3rd-max < TH) ~ e^-68
#define CAP 1024
#define NT 256
#define NW (NT / 32)
#define GRID_P 912         // 6 CTAs/SM x 152 SMs (GB300)
#define FX_SCALE 67108864.0f   // 2^26 fixed-point for the loss sum

__device__ unsigned long long g_loss_fx = 0ULL;
__device__ int                g_cnt_tot = 0;
__device__ unsigned int       g_done    = 0;

__device__ __forceinline__ float ex2f(float x) {
    float y; asm("ex2.approx.f32 %0, %1;" : "=f"(y) : "f"(x)); return y;
}
__device__ __forceinline__ float lg2f(float x) {
    float y; asm("lg2.approx.f32 %0, %1;" : "=f"(y) : "f"(x)); return y;
}

struct Top3 { float v0, v1, v2; int i0, i1, i2; };

// tie-aware "greater": value desc, index asc (matches jax top_k/argmax)
__device__ __forceinline__ bool gtv(float v, int i, float u, int j) {
    return (v > u) || (v == u && i < j);
}
__device__ __forceinline__ void ins_tie(float x, int idx, Top3& t) {
    if (!gtv(x, idx, t.v2, t.i2)) return;
    if (gtv(x, idx, t.v1, t.i1)) {
        t.v2 = t.v1; t.i2 = t.i1;
        if (gtv(x, idx, t.v0, t.i0)) { t.v1 = t.v0; t.i1 = t.i0; t.v0 = x; t.i0 = idx; }
        else                          { t.v1 = x;   t.i1 = idx; }
    } else { t.v2 = x; t.i2 = idx; }
}
// fallback-only insert (per-thread ascending indices, caller checked x > v2)
__device__ __forceinline__ void ins(float x, int idx, Top3& t) {
    if (x > t.v1) {
        t.v2 = t.v1; t.i2 = t.i1;
        if (x > t.v0) { t.v1 = t.v0; t.i1 = t.i0; t.v0 = x; t.i0 = idx; }
        else          { t.v1 = x;    t.i1 = idx; }
    } else { t.v2 = x; t.i2 = idx; }
}

__device__ __forceinline__ void warp_top3(Top3& t) {
    const unsigned full = 0xFFFFFFFFu;
    #pragma unroll
    for (int off = 16; off > 0; off >>= 1) {
        float bv0 = __shfl_down_sync(full, t.v0, off);
        float bv1 = __shfl_down_sync(full, t.v1, off);
        float bv2 = __shfl_down_sync(full, t.v2, off);
        int   bi0 = __shfl_down_sync(full, t.i0, off);
        int   bi1 = __shfl_down_sync(full, t.i1, off);
        int   bi2 = __shfl_down_sync(full, t.i2, off);
        ins_tie(bv0, bi0, t);
        ins_tie(bv1, bi1, t);
        ins_tie(bv2, bi2, t);
    }
}

__global__ void __launch_bounds__(NT)
hb_main(const float* __restrict__ yp, const int* __restrict__ y,
        float* __restrict__ out, int B, int C) {
    const int tid = threadIdx.x;
    const int wid = tid >> 5, lid = tid & 31;

    __shared__ float s_val[CAP];
    __shared__ int   s_idx[CAP];
    __shared__ int   s_cnt;
    __shared__ float ssum[NW];
    __shared__ float fv0[NW], fv1[NW], fv2[NW];
    __shared__ int   fi0[NW], fi1[NW], fi2[NW];

    #define APPEND(x, idx)                                        \
        if ((x) > CAND_TH) {                                      \
            int _p = atomicAdd(&s_cnt, 1);                        \
            if (_p < CAP) { s_val[_p] = (x); s_idx[_p] = (idx); } \
        }

    #define SUM4(v)                                          \
        s0 += ex2f((v).x * L2E);                             \
        s1 += ex2f((v).y * L2E);                             \
        s2 += ex2f((v).z * L2E);                             \
        s3 += ex2f((v).w * L2E);

    #define M4(v) fmaxf(fmaxf((v).x, (v).y), fmaxf((v).z, (v).w))

    #define CAND4(v, idx)                    \
        if (M4(v) > CAND_TH) {               \
            APPEND((v).x, (idx))             \
            APPEND((v).y, (idx) + 1)         \
            APPEND((v).z, (idx) + 2)         \
            APPEND((v).w, (idx) + 3)         \
        }

    for (int row = blockIdx.x; row < B; row += gridDim.x) {
        const float* base = yp + (size_t)row * (size_t)C;

        if (tid == 0) s_cnt = 0;
        __syncthreads();

        float s0 = 0.0f, s1 = 0.0f, s2 = 0.0f, s3 = 0.0f;

        // alignment lead-in for 16B float4 loads (row offset C=50257 is odd)
        int pre = (int)((4u - (unsigned)(((size_t)row * (size_t)C) & 3u)) & 3u);
        if (pre > C) pre = C;
        const int n4   = (C - pre) >> 2;
        const int tail = C - pre - (n4 << 2);

        for (int k = tid; k < pre; k += NT) {
            float x = __ldg(base + k);
            s0 += ex2f(x * L2E);
            APPEND(x, k)
        }

        const float4* b4 = reinterpret_cast<const float4*>(base + pre);
        int j = tid;
        // 4 independent LDG.128 issued before any consumer (MLP_p1 = 4)
        for (; j + 3 * NT < n4; j += 4 * NT) {
            float4 a = __ldcs(b4 + j);
            float4 b = __ldcs(b4 + j + NT);
            float4 c = __ldcs(b4 + j + 2 * NT);
            float4 d = __ldcs(b4 + j + 3 * NT);
            SUM4(a) SUM4(b) SUM4(c) SUM4(d)
            int ia = pre + (j << 2);
            CAND4(a, ia)
            CAND4(b, ia + 1 * (NT << 2))
            CAND4(c, ia + 2 * (NT << 2))
            CAND4(d, ia + 3 * (NT << 2))
        }
        for (; j < n4; j += NT) {
            float4 a = __ldcs(b4 + j);
            int ia = pre + (j << 2);
            SUM4(a)
            CAND4(a, ia)
        }

        for (int k = tid; k < tail; k += NT) {
            int idx = C - tail + k;
            float x = __ldg(base + idx);
            s0 += ex2f(x * L2E);
            APPEND(x, idx)
        }

        // ---- block-reduce the exp sum (deterministic order) ----
        float sum = (s0 + s1) + (s2 + s3);
        const unsigned full = 0xFFFFFFFFu;
        #pragma unroll
        for (int off = 16; off > 0; off >>= 1)
            sum += __shfl_down_sync(full, sum, off);
        if (lid == 0) ssum[wid] = sum;
        __syncthreads();          // also makes s_cnt / candidates visible

        const int cnt = s_cnt;    // block-uniform
        Top3 t;
        t.v0 = t.v1 = t.v2 = -FLT_MAX;
        t.i0 = t.i1 = t.i2 = 0x7FFFFFFF;

        if (cnt >= 3 && cnt <= CAP) {
            // ---- fast path: top-3 from candidate buffer (warp 0 only) ----
            if (wid == 0) {
                for (int p = lid; p < cnt; p += 32) {
                    float x = s_val[p]; int ix = s_idx[p];
                    if (gtv(x, ix, t.v2, t.i2)) ins_tie(x, ix, t);
                }
                warp_top3(t);
            }
        } else {
            // ---- exact fallback (statistically never taken) ----
            for (int k = tid; k < C; k += NT) {
                float x = __ldg(base + k);
                if (x > t.v2) ins(x, k, t);
            }
            warp_top3(t);
            if (lid == 0) {
                fv0[wid] = t.v0; fv1[wid] = t.v1; fv2[wid] = t.v2;
                fi0[wid] = t.i0; fi1[wid] = t.i1; fi2[wid] = t.i2;
            }
            __syncthreads();
            if (wid == 0) {
                if (lid < NW) {
                    t.v0 = fv0[lid]; t.v1 = fv1[lid]; t.v2 = fv2[lid];
                    t.i0 = fi0[lid]; t.i1 = fi1[lid]; t.i2 = fi2[lid];
                } else {
                    t.v0 = t.v1 = t.v2 = -FLT_MAX;
                    t.i0 = t.i1 = t.i2 = 0x7FFFFFFF;
                }
                warp_top3(t);
            }
        }

        if (wid == 0) {
            float z = (lid < NW) ? ssum[lid] : 0.0f;
            #pragma unroll
            for (int off = 16; off > 0; off >>= 1)
                z += __shfl_down_sync(full, z, off);

            if (lid == 0) {
                const float Z    = z;
                const float logZ = lg2f(Z) * LN2;
                const float rz   = 1.0f / Z;

                const int   ycol  = __ldg(y + row);
                const float fyl   = __ldg(base + ycol);
                const float fy    = ex2f(fyl * L2E) * rz;
                const int   sflag = (fy < 0.02f) ? 1 : 0;

                const float e0 = ex2f(t.v0 * L2E);
                const float e1 = ex2f(t.v1 * L2E);
                const float e2 = ex2f(t.v2 * L2E);
                const float wa = (t.v0 * e0 + t.v1 * e1 + t.v2 * e2) / (e0 + e1 + e2);

                const float loss = sflag ? (logZ - wa) : (logZ - fyl);

                out[1 + row]             = (float)sflag;
                out[1 + B + row]         = sflag ? (float)t.i0 : -1.0f; // s*z_max
                out[1 + 2 * B + row]     = sflag ? (float)t.i1 : -1.0f; // s*max9_d
                out[1 + 3 * B + row]     = sflag ? (float)t.i2 : -1.0f; // s*max8_d
                out[1 + 4 * B + 1 + row] = sflag ? (e1 * rz) : 0.0f;    // s*max_9

                // deterministic fixed-point accumulation (integer = associative)
                long long fx = llrintf(loss * FX_SCALE);
                atomicAdd(&g_loss_fx, (unsigned long long)fx);
                atomicAdd(&g_cnt_tot, 1 - sflag);
            }
        }
        __syncthreads();   // smem (s_val/s_cnt/ssum) safe for next row
    }

    // ---- completion ticket: ONE thread per CTA, one fence per CTA ----
    if (tid == 0) {
        __threadfence();   // order this CTA's atomics/stores before the ticket
        unsigned v = atomicAdd(&g_done, 1u);
        if (v == gridDim.x - 1) {
            long long lv = (long long)atomicExch(&g_loss_fx, 0ULL); // read+reset
            int       cv = atomicExch(&g_cnt_tot, 0);
            out[0]         = (float)((double)lv / (double)FX_SCALE / (double)B);
            out[1 + 4 * B] = (float)cv;
            g_done = 0;    // reset for next graph replay (kernel-exit fences this)
        }
    }
}

extern "C" void kernel_launch(void* const* d_in, const int* in_sizes, int n_in,
                              void* d_out, int out_size) {
    const float* yp = (const float*)d_in[0];   // y_pred, fp32 [B, C]
    const int*   y  = (const int*)d_in[1];     // labels, int32 [B]
    const int B = in_sizes[1];
    const int C = in_sizes[0] / B;
    float* out = (float*)d_out;

    int grid = (B < GRID_P) ? B : GRID_P;
    hb_main<<<grid, NT>>>(yp, y, out, B, C);
}